// round 3
// baseline (speedup 1.0000x reference)
#include <cuda_runtime.h>
#include <cstdint>
#include <math.h>

// Problem constants
#define BB     8
#define TLEN   2048
#define HIDD   1024
#define NHH    16
#define MDD    16
#define BT     (BB * TLEN)          // 16384 rows
#define N1     (NHH * MDD * MDD)    // 4096
#define K2D    (NHH * MDD * 2)      // 512

// Scratch (device globals — no allocation allowed)
// g_m : matrices in scan layout [s = b*16+nh][t][i*16+j], 256 MB
// g_x : scan output          [bt][nh*32 + dir*16 + i],    32 MB
__device__ float g_m[(size_t)BT * N1];
__device__ float g_x[(size_t)BT * K2D];

// ---------------------------------------------------------------------------
// Tiled SGEMM: C = A(MxK) * B(KxN) + bias, optional GELU, optional permuted
// store into scan layout (GEMM1 only; assumes N == 4096, M == 16384).
// BM=BN=128, BK=8, 256 threads, 8x8 micro-tile per thread.
// ---------------------------------------------------------------------------
template <bool PERM, bool GELU>
__global__ __launch_bounds__(256)
void sgemm_kernel(const float* __restrict__ A, const float* __restrict__ B,
                  const float* __restrict__ bias, float* __restrict__ C,
                  int M, int N, int K)
{
    const int BM = 128, BN = 128, BK = 8;
    __shared__ float As[BK][BM];   // transposed A tile
    __shared__ float Bs[BK][BN];

    const int tid = threadIdx.x;
    const int tx = tid & 15;       // 0..15 -> N micro
    const int ty = tid >> 4;       // 0..15 -> M micro
    const int bx = blockIdx.x;     // N tile
    const int by = blockIdx.y;     // M tile

    // Tile-load assignments (one float4 per thread per tile)
    const int aRow = tid >> 1;             // 0..127
    const int aCol = (tid & 1) * 4;        // 0 or 4
    const int bRow = tid >> 5;             // 0..7
    const int bCol = (tid & 31) * 4;       // 0..124

    const float* Ag = A + (size_t)(by * BM + aRow) * K + aCol;
    const float* Bg = B + (size_t)bRow * N + (size_t)bx * BN + bCol;

    float acc[8][8];
#pragma unroll
    for (int i = 0; i < 8; i++)
#pragma unroll
        for (int j = 0; j < 8; j++) acc[i][j] = 0.0f;

    for (int k0 = 0; k0 < K; k0 += BK) {
        float4 a4 = *(const float4*)(Ag + k0);
        float4 b4 = *(const float4*)(Bg + (size_t)k0 * N);

        As[aCol + 0][aRow] = a4.x;
        As[aCol + 1][aRow] = a4.y;
        As[aCol + 2][aRow] = a4.z;
        As[aCol + 3][aRow] = a4.w;
        *(float4*)&Bs[bRow][bCol] = b4;
        __syncthreads();

#pragma unroll
        for (int kk = 0; kk < BK; kk++) {
            float4 ra0 = *(const float4*)&As[kk][ty * 8];
            float4 ra1 = *(const float4*)&As[kk][ty * 8 + 4];
            float4 rb0 = *(const float4*)&Bs[kk][tx * 8];
            float4 rb1 = *(const float4*)&Bs[kk][tx * 8 + 4];
            float ra[8] = {ra0.x, ra0.y, ra0.z, ra0.w, ra1.x, ra1.y, ra1.z, ra1.w};
            float rb[8] = {rb0.x, rb0.y, rb0.z, rb0.w, rb1.x, rb1.y, rb1.z, rb1.w};
#pragma unroll
            for (int i = 0; i < 8; i++)
#pragma unroll
                for (int j = 0; j < 8; j++)
                    acc[i][j] = fmaf(ra[i], rb[j], acc[i][j]);
        }
        __syncthreads();
    }

    // Epilogue
    const int cbase = bx * BN + tx * 8;
    float bb[8];
#pragma unroll
    for (int j = 0; j < 8; j++) bb[j] = __ldg(&bias[cbase + j]);

#pragma unroll
    for (int i = 0; i < 8; i++) {
        const int row = by * BM + ty * 8 + i;
        float o[8];
#pragma unroll
        for (int j = 0; j < 8; j++) {
            float v = acc[i][j] + bb[j];
            if (GELU)
                v = 0.5f * v * (1.0f + erff(v * 0.70710678118654752f));
            o[j] = v;
        }
        if (PERM) {
            // row = bt -> (b, t); col group -> (nh, ij)
            const int b_ = row >> 11;
            const int t_ = row & (TLEN - 1);
            const int s  = (b_ << 4) + (cbase >> 8);
            const size_t off = ((size_t)s * TLEN + t_) * 256 + (cbase & 255);
            *(float4*)&C[off]     = make_float4(o[0], o[1], o[2], o[3]);
            *(float4*)&C[off + 4] = make_float4(o[4], o[5], o[6], o[7]);
        } else {
            const size_t off = (size_t)row * N + cbase;
            *(float4*)&C[off]     = make_float4(o[0], o[1], o[2], o[3]);
            *(float4*)&C[off + 4] = make_float4(o[4], o[5], o[6], o[7]);
        }
    }
}

// ---------------------------------------------------------------------------
// In-place Frobenius normalization: one warp per 16x16 matrix.
// m_norm = m / (||m||_F + 1e-5) * sqrt(16)
// ---------------------------------------------------------------------------
__global__ __launch_bounds__(256)
void fro_norm_kernel(float* __restrict__ m)
{
    const size_t mat = (size_t)blockIdx.x * 8 + (threadIdx.x >> 5);
    const int lane = threadIdx.x & 31;
    float* p = m + mat * 256 + lane * 8;
    float4 a = *(float4*)p;
    float4 b = *(float4*)(p + 4);
    float ss = a.x * a.x + a.y * a.y + a.z * a.z + a.w * a.w
             + b.x * b.x + b.y * b.y + b.z * b.z + b.w * b.w;
    ss += __shfl_xor_sync(0xffffffffu, ss, 16);
    ss += __shfl_xor_sync(0xffffffffu, ss, 8);
    ss += __shfl_xor_sync(0xffffffffu, ss, 4);
    ss += __shfl_xor_sync(0xffffffffu, ss, 2);
    ss += __shfl_xor_sync(0xffffffffu, ss, 1);
    const float sc = 4.0f / (sqrtf(ss) + 1e-5f);
    a.x *= sc; a.y *= sc; a.z *= sc; a.w *= sc;
    b.x *= sc; b.y *= sc; b.z *= sc; b.w *= sc;
    *(float4*)p = a;
    *(float4*)(p + 4) = b;
}

// ---------------------------------------------------------------------------
// Sequential normalized-matvec scan. One warp per (sequence, direction).
// Lane l: row i = l&15, column half h = l>>4 (cols 8h..8h+7).
// v distributed as v[l&15] (duplicated in lanes 16..31).
// Grid: 128 blocks x 64 threads (block = one sequence, warp 0 = lr, warp 1 = rl)
// ---------------------------------------------------------------------------
__global__ __launch_bounds__(64)
void scan_kernel(const float* __restrict__ mn, float* __restrict__ x)
{
    const unsigned F = 0xffffffffu;
    const int warp = threadIdx.x >> 5;
    const int lane = threadIdx.x & 31;
    const int s = blockIdx.x;          // 0..127 (= b*16 + nh)
    const int d = warp;                // 0 = lr, 1 = rl
    const int b = s >> 4;
    const int nh = s & 15;

    const int laneoff = (lane & 15) * 16 + (lane >> 4) * 8;
    const float* base = mn + (size_t)s * (TLEN * 256) + laneoff;
    const int h8 = (lane >> 4) << 3;

    const int t0 = d ? (TLEN - 1) : 0;
    const int dt = d ? -1 : 1;

    float v = ((lane & 15) == 0) ? 1.0f : 0.0f;

    float* xout = x + (size_t)b * TLEN * 512 + nh * 32 + d * 16 + (lane & 15);

    // prime double buffer
    const float* p0 = base + (size_t)t0 * 256;
    float4 c0 = __ldg((const float4*)p0);
    float4 c1 = __ldg((const float4*)(p0 + 4));

#pragma unroll 1
    for (int step = 0; step < TLEN; ++step) {
        const int t = t0 + step * dt;
        int tn = t + dt;
        tn = tn < 0 ? 0 : (tn > TLEN - 1 ? TLEN - 1 : tn);
        const float* q = base + (size_t)tn * 256;
        float4 n0 = __ldg((const float4*)q);
        float4 n1 = __ldg((const float4*)(q + 4));

        // broadcast v[h8..h8+7]
        const float vb0 = __shfl_sync(F, v, h8 + 0);
        const float vb1 = __shfl_sync(F, v, h8 + 1);
        const float vb2 = __shfl_sync(F, v, h8 + 2);
        const float vb3 = __shfl_sync(F, v, h8 + 3);
        const float vb4 = __shfl_sync(F, v, h8 + 4);
        const float vb5 = __shfl_sync(F, v, h8 + 5);
        const float vb6 = __shfl_sync(F, v, h8 + 6);
        const float vb7 = __shfl_sync(F, v, h8 + 7);

        float pA = c0.x * vb0;
        pA = fmaf(c0.y, vb1, pA);
        pA = fmaf(c0.z, vb2, pA);
        pA = fmaf(c0.w, vb3, pA);
        float pB = c1.x * vb4;
        pB = fmaf(c1.y, vb5, pB);
        pB = fmaf(c1.z, vb6, pB);
        pB = fmaf(c1.w, vb7, pB);
        float pp = pA + pB;

        // combine column halves: lanes i and i+16 both get nv[i]
        const float nv = pp + __shfl_xor_sync(F, pp, 16);

        // squared-norm butterfly over 16 distinct values
        float ss = nv * nv;
        ss += __shfl_xor_sync(F, ss, 8);
        ss += __shfl_xor_sync(F, ss, 4);
        ss += __shfl_xor_sync(F, ss, 2);
        ss += __shfl_xor_sync(F, ss, 1);

        v = nv * (1.0f / (sqrtf(ss) + 1e-6f));

        if (lane < 16)
            xout[(size_t)t * 512] = v;

        c0 = n0;
        c1 = n1;
    }
}

// ---------------------------------------------------------------------------
// Launch
// ---------------------------------------------------------------------------
extern "C" void kernel_launch(void* const* d_in, const int* in_sizes, int n_in,
                              void* d_out, int out_size)
{
    const float* hs = (const float*)d_in[0];   // (B,T,HID)
    const float* Wm = (const float*)d_in[1];   // (HID, 4096)
    const float* bm = (const float*)d_in[2];   // (4096,)
    const float* Wo = (const float*)d_in[3];   // (512, 1024)
    const float* bo = (const float*)d_in[4];   // (1024,)
    float* out = (float*)d_out;                // (B,T,HID)

    float *pm = nullptr, *px = nullptr;
    cudaGetSymbolAddress((void**)&pm, g_m);
    cudaGetSymbolAddress((void**)&px, g_x);

    // 1) GEMM1: m = hs @ W_mat + b_mat, scattered into scan layout
    sgemm_kernel<true, false><<<dim3(N1 / 128, BT / 128), 256>>>(
        hs, Wm, bm, pm, BT, N1, HIDD);

    // 2) In-place Frobenius normalization (262144 matrices, warp each)
    fro_norm_kernel<<<(BT * NHH) / 8, 256>>>(pm);

    // 3) Bidirectional normalized-matvec scan
    scan_kernel<<<128, 64>>>(pm, px);

    // 4) GEMM2: out = gelu(x @ W_out + b_out)
    sgemm_kernel<false, true><<<dim3(HIDD / 128, BT / 128), 256>>>(
        px, Wo, bo, out, BT, HIDD, K2D);
}

// round 6
// speedup vs baseline: 1.1155x; 1.1155x over previous
#include <cuda_runtime.h>
#include <cuda_bf16.h>
#include <cstdint>
#include <math.h>

// Problem constants
#define BB     8
#define TLEN   2048
#define HIDD   1024
#define NHH    16
#define MDD    16
#define BT     (BB * TLEN)          // 16384 rows
#define N1     (NHH * MDD * MDD)    // 4096
#define K2D    (NHH * MDD * 2)      // 512

// ---------------------------------------------------------------------------
// Scratch (device globals — no allocation allowed)
// ---------------------------------------------------------------------------
__device__ float g_m[(size_t)BT * N1];                 // scan layout [s][t][256]
__device__ float g_x[(size_t)BT * K2D];                // scan output
__device__ __nv_bfloat16 g_ah[(size_t)BT * HIDD];      // hs hi
__device__ __nv_bfloat16 g_am[(size_t)BT * HIDD];      // hs mid
__device__ __nv_bfloat16 g_al[(size_t)BT * HIDD];      // hs lo
__device__ __nv_bfloat16 g_bh[(size_t)N1 * HIDD];      // W_mat^T hi  [n][k]
__device__ __nv_bfloat16 g_bm[(size_t)N1 * HIDD];      // W_mat^T mid [n][k]
__device__ __nv_bfloat16 g_bl[(size_t)N1 * HIDD];      // W_mat^T lo  [n][k]

// ---------------------------------------------------------------------------
// Helpers
// ---------------------------------------------------------------------------
__device__ __forceinline__ uint32_t smem_u32(const void* p) {
    uint32_t a;
    asm("{ .reg .u64 t; cvta.to.shared.u64 t, %1; cvt.u32.u64 %0, t; }" : "=r"(a) : "l"(p));
    return a;
}
#define CP_ASYNC16(dst, src) \
    asm volatile("cp.async.cg.shared.global [%0], [%1], 16;\n" :: "r"(dst), "l"(src) : "memory")
#define CP_COMMIT()  asm volatile("cp.async.commit_group;\n" ::: "memory")
#define CP_WAIT3()   asm volatile("cp.async.wait_group 3;\n" ::: "memory")

__device__ __forceinline__ void ldsm_x4(uint32_t& r0, uint32_t& r1, uint32_t& r2,
                                        uint32_t& r3, uint32_t addr) {
    asm volatile("ldmatrix.sync.aligned.m8n8.x4.shared.b16 {%0,%1,%2,%3}, [%4];"
                 : "=r"(r0), "=r"(r1), "=r"(r2), "=r"(r3) : "r"(addr));
}
__device__ __forceinline__ void mma_bf16(float* c, const uint32_t* a, const uint32_t* b) {
    asm volatile(
        "mma.sync.aligned.m16n8k16.row.col.f32.bf16.bf16.f32 "
        "{%0,%1,%2,%3}, {%4,%5,%6,%7}, {%8,%9}, {%0,%1,%2,%3};"
        : "+f"(c[0]), "+f"(c[1]), "+f"(c[2]), "+f"(c[3])
        : "r"(a[0]), "r"(a[1]), "r"(a[2]), "r"(a[3]), "r"(b[0]), "r"(b[1]));
}
__device__ __forceinline__ uint32_t swz(uint32_t off) { return off ^ ((off >> 3) & 0x70); }

// ---------------------------------------------------------------------------
// Conversion kernels: 3-term bf16 split (hi + mid + lo ~= 24+ mantissa bits)
// ---------------------------------------------------------------------------
struct alignas(8) bf4 { __nv_bfloat16 v[4]; };

__global__ __launch_bounds__(256)
void convA_kernel(const float* __restrict__ x, __nv_bfloat16* __restrict__ hi,
                  __nv_bfloat16* __restrict__ mi, __nv_bfloat16* __restrict__ lo)
{
    const int i = blockIdx.x * blockDim.x + threadIdx.x;   // float4 index
    float4 v = ((const float4*)x)[i];
    bf4 h, m, l;
    float a[4] = {v.x, v.y, v.z, v.w};
#pragma unroll
    for (int j = 0; j < 4; j++) {
        __nv_bfloat16 hb = __float2bfloat16_rn(a[j]);
        float r1 = a[j] - __bfloat162float(hb);
        __nv_bfloat16 mb = __float2bfloat16_rn(r1);
        float r2 = r1 - __bfloat162float(mb);
        h.v[j] = hb;
        m.v[j] = mb;
        l.v[j] = __float2bfloat16_rn(r2);
    }
    ((bf4*)hi)[i] = h;
    ((bf4*)mi)[i] = m;
    ((bf4*)lo)[i] = l;
}

// Transpose W_mat (1024 x 4096) -> [n][k] bf16 hi/mid/lo
__global__ __launch_bounds__(1024)
void convB_kernel(const float* __restrict__ W, __nv_bfloat16* __restrict__ bh,
                  __nv_bfloat16* __restrict__ bm, __nv_bfloat16* __restrict__ bl)
{
    __shared__ float tile[32][33];
    const int n_in = blockIdx.x * 32 + threadIdx.x;
    const int k_in = blockIdx.y * 32 + threadIdx.y;
    tile[threadIdx.y][threadIdx.x] = W[(size_t)k_in * N1 + n_in];
    __syncthreads();
    const int n_out = blockIdx.x * 32 + threadIdx.y;
    const int k_out = blockIdx.y * 32 + threadIdx.x;
    const float v = tile[threadIdx.x][threadIdx.y];
    __nv_bfloat16 hb = __float2bfloat16_rn(v);
    float r1 = v - __bfloat162float(hb);
    __nv_bfloat16 mb = __float2bfloat16_rn(r1);
    float r2 = r1 - __bfloat162float(mb);
    const size_t o = (size_t)n_out * HIDD + k_out;
    bh[o] = hb;
    bm[o] = mb;
    bl[o] = __float2bfloat16_rn(r2);
}

// ---------------------------------------------------------------------------
// GEMM1 via HMMA (mma.sync bf16), 6-product 3-term split:
// D = Ah*Bh + Ah*Bm + Am*Bh + Ah*Bl + Am*Bm + Al*Bh  (+bias),
// permuted store into scan layout. CTA tile 128x128, 8 warps (2m x 4n),
// warp tile 64x32. 4-stage cp.async ring, K-chunk = 64.
// Grid: (32, 128). 256 threads.
// ---------------------------------------------------------------------------
#define STAGE_BYTES 32768            // A 16KB + B 16KB
#define GEMM1_SMEM  (1024 + 4 * STAGE_BYTES)
#define NPASS       6
#define NITER       (NPASS * 16)     // 6 passes * 16 chunks

__global__ __launch_bounds__(256)
void gemm1_mma_kernel(const __nv_bfloat16* __restrict__ Ah,
                      const __nv_bfloat16* __restrict__ Am,
                      const __nv_bfloat16* __restrict__ Al,
                      const __nv_bfloat16* __restrict__ Bh,
                      const __nv_bfloat16* __restrict__ Bm,
                      const __nv_bfloat16* __restrict__ Bl,
                      const float* __restrict__ bias,
                      float* __restrict__ C)
{
    extern __shared__ char smem[];
    const uint32_t tiles = (smem_u32(smem) + 1023u) & ~1023u;
    const int tid = threadIdx.x;
    const int lane = tid & 31, warp = tid >> 5;
    const int wm = warp & 1, wn = warp >> 1;     // 2 x 4 warp grid
    const int bx = blockIdx.x;                   // N tile (0..31)
    const int by = blockIdx.y;                   // M tile (0..127)

    const __nv_bfloat16* Asrc[NPASS] = {Ah, Ah, Am, Ah, Am, Al};
    const __nv_bfloat16* Bsrc[NPASS] = {Bh, Bm, Bh, Bl, Bm, Bh};

    // cp.async assignment: 256 threads, 16B each, 32 rows per pass
    const int lr = tid >> 3;           // 0..31
    const int lc = (tid & 7) * 16;     // byte col in 128B row

    auto issue_loads = [&](int iter) {
        const int pass = iter >> 4, chunk = iter & 15, stage = iter & 3;
        const uint32_t a_s = tiles + stage * STAGE_BYTES;
        const uint32_t b_s = a_s + 16384;
        const __nv_bfloat16* Ap = Asrc[pass] + (size_t)(by * 128) * HIDD + chunk * 64 + (lc >> 1);
        const __nv_bfloat16* Bp = Bsrc[pass] + (size_t)(bx * 128) * HIDD + chunk * 64 + (lc >> 1);
#pragma unroll
        for (int it = 0; it < 4; it++) {
            const int row = it * 32 + lr;
            CP_ASYNC16(a_s + swz(row * 128 + lc), Ap + (size_t)row * HIDD);
        }
#pragma unroll
        for (int it = 0; it < 4; it++) {
            const int row = it * 32 + lr;
            CP_ASYNC16(b_s + swz(row * 128 + lc), Bp + (size_t)row * HIDD);
        }
    };

    float acc[4][4][4];
#pragma unroll
    for (int i = 0; i < 4; i++)
#pragma unroll
        for (int j = 0; j < 4; j++)
#pragma unroll
            for (int k = 0; k < 4; k++) acc[i][j][k] = 0.0f;

    // ldmatrix lane addressing: row = base + (lane&15), koff = (lane>>4)*16 bytes
    const int lrow = lane & 15;
    const int lkof = (lane >> 4) * 16;

    for (int j = 0; j < 4; j++) { issue_loads(j); CP_COMMIT(); }

    for (int i = 0; i < NITER; i++) {
        CP_WAIT3();
        __syncthreads();
        const uint32_t a_s = tiles + (i & 3) * STAGE_BYTES;
        const uint32_t b_s = a_s + 16384;

#pragma unroll
        for (int ks = 0; ks < 4; ks++) {
            const int kb = ks * 32 + lkof;       // byte offset of 8-half block
            uint32_t a[4][4], b[4][2];
#pragma unroll
            for (int mt = 0; mt < 4; mt++) {
                const int row = wm * 64 + mt * 16 + lrow;
                ldsm_x4(a[mt][0], a[mt][1], a[mt][2], a[mt][3],
                        a_s + swz(row * 128 + kb));
            }
#pragma unroll
            for (int bt = 0; bt < 2; bt++) {
                const int row = wn * 32 + bt * 16 + lrow;
                uint32_t r0, r1, r2, r3;
                ldsm_x4(r0, r1, r2, r3, b_s + swz(row * 128 + kb));
                b[bt * 2 + 0][0] = r0; b[bt * 2 + 1][0] = r1;
                b[bt * 2 + 0][1] = r2; b[bt * 2 + 1][1] = r3;
            }
#pragma unroll
            for (int mt = 0; mt < 4; mt++)
#pragma unroll
                for (int nt = 0; nt < 4; nt++)
                    mma_bf16(acc[mt][nt], a[mt], b[nt]);
        }
        __syncthreads();
        if (i + 4 < NITER) issue_loads(i + 4);
        CP_COMMIT();
    }

    // ---- epilogue: bias + permuted store into scan layout ----
    const int g = lane >> 2, t4 = lane & 3;
#pragma unroll
    for (int mt = 0; mt < 4; mt++) {
#pragma unroll
        for (int nt = 0; nt < 4; nt++) {
            const int rm = by * 128 + wm * 64 + mt * 16 + g;
            const int cg = bx * 128 + wn * 32 + nt * 8 + t4 * 2;
            const int nh = cg >> 8, ij = cg & 255;
            const float b0 = __ldg(&bias[cg]);
            const float b1 = __ldg(&bias[cg + 1]);
            const int b_ = rm >> 11, t_ = rm & (TLEN - 1);
            float* o = C + (((size_t)(b_ * 16 + nh) * TLEN + t_) * 256 + ij);
            *(float2*)o = make_float2(acc[mt][nt][0] + b0, acc[mt][nt][1] + b1);
            *(float2*)(o + 8 * 256) = make_float2(acc[mt][nt][2] + b0, acc[mt][nt][3] + b1);
        }
    }
}

// ---------------------------------------------------------------------------
// In-place Frobenius normalization: one warp per 16x16 matrix.
// ---------------------------------------------------------------------------
__global__ __launch_bounds__(256)
void fro_norm_kernel(float* __restrict__ m)
{
    const size_t mat = (size_t)blockIdx.x * 8 + (threadIdx.x >> 5);
    const int lane = threadIdx.x & 31;
    float* p = m + mat * 256 + lane * 8;
    float4 a = *(float4*)p;
    float4 b = *(float4*)(p + 4);
    float ss = a.x * a.x + a.y * a.y + a.z * a.z + a.w * a.w
             + b.x * b.x + b.y * b.y + b.z * b.z + b.w * b.w;
    ss += __shfl_xor_sync(0xffffffffu, ss, 16);
    ss += __shfl_xor_sync(0xffffffffu, ss, 8);
    ss += __shfl_xor_sync(0xffffffffu, ss, 4);
    ss += __shfl_xor_sync(0xffffffffu, ss, 2);
    ss += __shfl_xor_sync(0xffffffffu, ss, 1);
    const float sc = 4.0f / (sqrtf(ss) + 1e-5f);
    a.x *= sc; a.y *= sc; a.z *= sc; a.w *= sc;
    b.x *= sc; b.y *= sc; b.z *= sc; b.w *= sc;
    *(float4*)p = a;
    *(float4*)(p + 4) = b;
}

// ---------------------------------------------------------------------------
// Sequential normalized-matvec scan. One warp per (sequence, direction).
// ---------------------------------------------------------------------------
__global__ __launch_bounds__(64)
void scan_kernel(const float* __restrict__ mn, float* __restrict__ x)
{
    const unsigned F = 0xffffffffu;
    const int warp = threadIdx.x >> 5;
    const int lane = threadIdx.x & 31;
    const int s = blockIdx.x;
    const int d = warp;
    const int b = s >> 4;
    const int nh = s & 15;

    const int laneoff = (lane & 15) * 16 + (lane >> 4) * 8;
    const float* base = mn + (size_t)s * (TLEN * 256) + laneoff;
    const int h8 = (lane >> 4) << 3;

    const int t0 = d ? (TLEN - 1) : 0;
    const int dt = d ? -1 : 1;

    float v = ((lane & 15) == 0) ? 1.0f : 0.0f;
    float* xout = x + (size_t)b * TLEN * 512 + nh * 32 + d * 16 + (lane & 15);

    const float* p0 = base + (size_t)t0 * 256;
    float4 c0 = __ldg((const float4*)p0);
    float4 c1 = __ldg((const float4*)(p0 + 4));

#pragma unroll 1
    for (int step = 0; step < TLEN; ++step) {
        const int t = t0 + step * dt;
        int tn = t + dt;
        tn = tn < 0 ? 0 : (tn > TLEN - 1 ? TLEN - 1 : tn);
        const float* q = base + (size_t)tn * 256;
        float4 n0 = __ldg((const float4*)q);
        float4 n1 = __ldg((const float4*)(q + 4));

        const float vb0 = __shfl_sync(F, v, h8 + 0);
        const float vb1 = __shfl_sync(F, v, h8 + 1);
        const float vb2 = __shfl_sync(F, v, h8 + 2);
        const float vb3 = __shfl_sync(F, v, h8 + 3);
        const float vb4 = __shfl_sync(F, v, h8 + 4);
        const float vb5 = __shfl_sync(F, v, h8 + 5);
        const float vb6 = __shfl_sync(F, v, h8 + 6);
        const float vb7 = __shfl_sync(F, v, h8 + 7);

        float pA = c0.x * vb0;
        pA = fmaf(c0.y, vb1, pA);
        pA = fmaf(c0.z, vb2, pA);
        pA = fmaf(c0.w, vb3, pA);
        float pB = c1.x * vb4;
        pB = fmaf(c1.y, vb5, pB);
        pB = fmaf(c1.z, vb6, pB);
        pB = fmaf(c1.w, vb7, pB);
        float pp = pA + pB;

        const float nv = pp + __shfl_xor_sync(F, pp, 16);

        float ss = nv * nv;
        ss += __shfl_xor_sync(F, ss, 8);
        ss += __shfl_xor_sync(F, ss, 4);
        ss += __shfl_xor_sync(F, ss, 2);
        ss += __shfl_xor_sync(F, ss, 1);

        v = nv * (1.0f / (sqrtf(ss) + 1e-6f));

        if (lane < 16)
            xout[(size_t)t * 512] = v;

        c0 = n0;
        c1 = n1;
    }
}

// ---------------------------------------------------------------------------
// Tiled SGEMM (GEMM2): C = gelu(A(MxK)*B(KxN) + bias)
// ---------------------------------------------------------------------------
__global__ __launch_bounds__(256)
void sgemm_gelu_kernel(const float* __restrict__ A, const float* __restrict__ B,
                       const float* __restrict__ bias, float* __restrict__ C,
                       int M, int N, int K)
{
    const int BM = 128, BN = 128, BK = 8;
    __shared__ float As[BK][BM];
    __shared__ float Bs[BK][BN];

    const int tid = threadIdx.x;
    const int tx = tid & 15, ty = tid >> 4;
    const int bx = blockIdx.x, by = blockIdx.y;

    const int aRow = tid >> 1, aCol = (tid & 1) * 4;
    const int bRow = tid >> 5, bCol = (tid & 31) * 4;

    const float* Ag = A + (size_t)(by * BM + aRow) * K + aCol;
    const float* Bg = B + (size_t)bRow * N + (size_t)bx * BN + bCol;

    float acc[8][8];
#pragma unroll
    for (int i = 0; i < 8; i++)
#pragma unroll
        for (int j = 0; j < 8; j++) acc[i][j] = 0.0f;

    for (int k0 = 0; k0 < K; k0 += BK) {
        float4 a4 = *(const float4*)(Ag + k0);
        float4 b4 = *(const float4*)(Bg + (size_t)k0 * N);
        As[aCol + 0][aRow] = a4.x;
        As[aCol + 1][aRow] = a4.y;
        As[aCol + 2][aRow] = a4.z;
        As[aCol + 3][aRow] = a4.w;
        *(float4*)&Bs[bRow][bCol] = b4;
        __syncthreads();
#pragma unroll
        for (int kk = 0; kk < BK; kk++) {
            float4 ra0 = *(const float4*)&As[kk][ty * 8];
            float4 ra1 = *(const float4*)&As[kk][ty * 8 + 4];
            float4 rb0 = *(const float4*)&Bs[kk][tx * 8];
            float4 rb1 = *(const float4*)&Bs[kk][tx * 8 + 4];
            float ra[8] = {ra0.x, ra0.y, ra0.z, ra0.w, ra1.x, ra1.y, ra1.z, ra1.w};
            float rb[8] = {rb0.x, rb0.y, rb0.z, rb0.w, rb1.x, rb1.y, rb1.z, rb1.w};
#pragma unroll
            for (int i = 0; i < 8; i++)
#pragma unroll
                for (int j = 0; j < 8; j++)
                    acc[i][j] = fmaf(ra[i], rb[j], acc[i][j]);
        }
        __syncthreads();
    }

    const int cbase = bx * BN + tx * 8;
    float bb[8];
#pragma unroll
    for (int j = 0; j < 8; j++) bb[j] = __ldg(&bias[cbase + j]);

#pragma unroll
    for (int i = 0; i < 8; i++) {
        const int rowi = by * BM + ty * 8 + i;
        float o[8];
#pragma unroll
        for (int j = 0; j < 8; j++) {
            float v = acc[i][j] + bb[j];
            o[j] = 0.5f * v * (1.0f + erff(v * 0.70710678118654752f));
        }
        const size_t off = (size_t)rowi * N + cbase;
        *(float4*)&C[off]     = make_float4(o[0], o[1], o[2], o[3]);
        *(float4*)&C[off + 4] = make_float4(o[4], o[5], o[6], o[7]);
    }
}

// ---------------------------------------------------------------------------
// Launch
// ---------------------------------------------------------------------------
extern "C" void kernel_launch(void* const* d_in, const int* in_sizes, int n_in,
                              void* d_out, int out_size)
{
    const float* hs = (const float*)d_in[0];
    const float* Wm = (const float*)d_in[1];
    const float* bm = (const float*)d_in[2];
    const float* Wo = (const float*)d_in[3];
    const float* bo = (const float*)d_in[4];
    float* out = (float*)d_out;

    float *pm, *px;
    __nv_bfloat16 *pah, *pam, *pal, *pbh, *pbm, *pbl;
    cudaGetSymbolAddress((void**)&pm, g_m);
    cudaGetSymbolAddress((void**)&px, g_x);
    cudaGetSymbolAddress((void**)&pah, g_ah);
    cudaGetSymbolAddress((void**)&pam, g_am);
    cudaGetSymbolAddress((void**)&pal, g_al);
    cudaGetSymbolAddress((void**)&pbh, g_bh);
    cudaGetSymbolAddress((void**)&pbm, g_bm);
    cudaGetSymbolAddress((void**)&pbl, g_bl);

    // 0) 3-term bf16 splits
    convA_kernel<<<(BT * HIDD / 4) / 256, 256>>>(hs, pah, pam, pal);
    convB_kernel<<<dim3(N1 / 32, HIDD / 32), dim3(32, 32)>>>(Wm, pbh, pbm, pbl);

    // 1) GEMM1 on tensor cores (HMMA, 6-product split) -> scan layout (+bias)
    cudaFuncSetAttribute(gemm1_mma_kernel,
                         cudaFuncAttributeMaxDynamicSharedMemorySize, GEMM1_SMEM);
    gemm1_mma_kernel<<<dim3(N1 / 128, BT / 128), 256, GEMM1_SMEM>>>(
        pah, pam, pal, pbh, pbm, pbl, bm, pm);

    // 2) In-place Frobenius normalization
    fro_norm_kernel<<<(BT * NHH) / 8, 256>>>(pm);

    // 3) Bidirectional normalized-matvec scan
    scan_kernel<<<128, 64>>>(pm, px);

    // 4) GEMM2: out = gelu(x @ W_out + b_out)
    sgemm_gelu_kernel<<<dim3(HIDD / 128, BT / 128), 256>>>(
        px, Wo, bo, out, BT, HIDD, K2D);
}